// round 15
// baseline (speedup 1.0000x reference)
#include <cuda_runtime.h>
#include <cstdint>

// Max-unpool scatter, deterministic last-index-wins (matches reference).
//
// Round-15: R5 champion (134.8us) byte-exact + ONE addition — the scatter
// kernel prefetches x into L2 (prefetch.global.L2, one per 128B line, every
// 4th thread). S is atomic-latency-bound with idle issue slots and runs
// immediately before compact, so compact's ~6M random x-gathers start as
// L2 hits instead of DRAM misses.
//   Z: 4 consecutive uint4/thread (R5 exact; slow form empirically beats
//      the fast coalesced form by ~5us net via S+C coupling)
//   S: atomicMax(scr[pos[i]], i+1), 8 atomics/thread, pos __ldcs,
//      + x L2 prefetch
//   C: linear 8/thread; scratch __ldcs, x __ldg, out __stcs (R5 exact)

#define N_OUT_CONST 25690112  // 32*112*112*64

__device__ unsigned int g_winner[N_OUT_CONST];

// R5's exact zero form: count16 threads, each writes 4 consecutive uint4.
__global__ void zero_scratch_kernel(int count16) {
    int t = blockIdx.x * blockDim.x + threadIdx.x;
    if (t < count16) {
        uint4* p = reinterpret_cast<uint4*>(g_winner) + 4 * t;
        uint4 z = make_uint4(0u, 0u, 0u, 0u);
        p[0] = z; p[1] = z; p[2] = z; p[3] = z;
    }
}

// n8 = n/8 threads, each loads 2 int4 of pos and issues 8 fire-and-forget
// RED.MAX. Every 4th thread additionally prefetches one 128B line of x
// (thread t covers x[8t..8t+7] = 32B; 4 threads = 128B line), so all of x
// (n floats) is L2-resident when compact launches.
__global__ void scatter_kernel(const int4* __restrict__ p4,
                               const float* __restrict__ x, int n8) {
    int t = blockIdx.x * blockDim.x + threadIdx.x;
    if (t >= n8) return;
    int4 a = __ldcs(&p4[2 * t + 0]);
    int4 b = __ldcs(&p4[2 * t + 1]);

    if ((t & 3) == 0) {
        asm volatile("prefetch.global.L2 [%0];" :: "l"(x + 8 * (size_t)t));
    }

    unsigned int base = (unsigned int)(t * 8);
    atomicMax(&g_winner[a.x], base + 1u);
    atomicMax(&g_winner[a.y], base + 2u);
    atomicMax(&g_winner[a.z], base + 3u);
    atomicMax(&g_winner[a.w], base + 4u);
    atomicMax(&g_winner[b.x], base + 5u);
    atomicMax(&g_winner[b.y], base + 6u);
    atomicMax(&g_winner[b.z], base + 7u);
    atomicMax(&g_winner[b.w], base + 8u);
}

// Linear form: thread t consumes uint4 slots 2t, 2t+1, 8 gathers batched,
// 2 float4 streaming stores.
__global__ void compact_kernel(float* __restrict__ out,
                               const float* __restrict__ x,
                               int count8) {
    int t = blockIdx.x * blockDim.x + threadIdx.x;
    if (t >= count8) return;

    const uint4* __restrict__ sp = reinterpret_cast<const uint4*>(g_winner);
    float4* __restrict__ op = reinterpret_cast<float4*>(out);

    uint4 w0 = __ldcs(&sp[2 * t + 0]);
    uint4 w1 = __ldcs(&sp[2 * t + 1]);

    float4 o0, o1;
    o0.x = w0.x ? __ldg(&x[w0.x - 1u]) : 0.0f;
    o0.y = w0.y ? __ldg(&x[w0.y - 1u]) : 0.0f;
    o0.z = w0.z ? __ldg(&x[w0.z - 1u]) : 0.0f;
    o0.w = w0.w ? __ldg(&x[w0.w - 1u]) : 0.0f;
    o1.x = w1.x ? __ldg(&x[w1.x - 1u]) : 0.0f;
    o1.y = w1.y ? __ldg(&x[w1.y - 1u]) : 0.0f;
    o1.z = w1.z ? __ldg(&x[w1.z - 1u]) : 0.0f;
    o1.w = w1.w ? __ldg(&x[w1.w - 1u]) : 0.0f;

    __stcs(&op[2 * t + 0], o0);
    __stcs(&op[2 * t + 1], o1);
}

extern "C" void kernel_launch(void* const* d_in, const int* in_sizes, int n_in,
                              void* d_out, int out_size) {
    const float* x = reinterpret_cast<const float*>(d_in[0]);
    const int* pos = reinterpret_cast<const int*>(d_in[1]);
    float* out     = reinterpret_cast<float*>(d_out);

    int n = in_sizes[0];             // 6,422,528 (divisible by 8)
    int n8 = n / 8;                  // 802,816
    int count16 = out_size / 16;     // 1,605,632
    int count8  = out_size / 8;      // 3,211,264

    const int T = 256;

    // Z: zero the winner scratch (heats it in L2 right before the atomics).
    zero_scratch_kernel<<<(count16 + T - 1) / T, T>>>(count16);

    // S: deterministic last-index-wins via 32-bit atomicMax, 8/thread,
    //    + x prefetch into L2 for the compact that follows.
    scatter_kernel<<<(n8 + T - 1) / T, T>>>(
        reinterpret_cast<const int4*>(pos), x, n8);

    // C: gather winners' values, zero-fill empties, stream out.
    compact_kernel<<<(count8 + T - 1) / T, T>>>(out, x, count8);
}

// round 16
// speedup vs baseline: 1.1398x; 1.1398x over previous
#include <cuda_runtime.h>
#include <cstdint>

// Max-unpool scatter, deterministic last-index-wins (matches reference).
//
// Round-16: BYTE-EXACT re-bench of the Round-5 champion (134.8us).
// Eight consecutive single-change deviations (R6-R15) all regressed or were
// neutral; per rigor.md, re-bench before claiming the champion number.
//   Z: zero scratch, 4x consecutive uint4/thread
//   S: atomicMax(scr[pos[i]], i+1), 8 atomics/thread, pos via __ldcs
//   C: linear 8/thread; scratch __ldcs, x __ldg, out __stcs

#define N_OUT_CONST 25690112  // 32*112*112*64

__device__ unsigned int g_winner[N_OUT_CONST];

// count16 = N_OUT/16 threads, each writes 4 consecutive uint4 (64B).
__global__ void zero_scratch_kernel(int count16) {
    int t = blockIdx.x * blockDim.x + threadIdx.x;
    if (t < count16) {
        uint4* p = reinterpret_cast<uint4*>(g_winner) + 4 * t;
        uint4 z = make_uint4(0u, 0u, 0u, 0u);
        p[0] = z; p[1] = z; p[2] = z; p[3] = z;
    }
}

// n8 = n/8 threads, each loads 2 int4 of pos and issues 8 atomics.
__global__ void scatter_kernel(const int4* __restrict__ p4, int n8) {
    int t = blockIdx.x * blockDim.x + threadIdx.x;
    if (t >= n8) return;
    int4 a = __ldcs(&p4[2 * t + 0]);
    int4 b = __ldcs(&p4[2 * t + 1]);
    unsigned int base = (unsigned int)(t * 8);
    atomicMax(&g_winner[a.x], base + 1u);
    atomicMax(&g_winner[a.y], base + 2u);
    atomicMax(&g_winner[a.z], base + 3u);
    atomicMax(&g_winner[a.w], base + 4u);
    atomicMax(&g_winner[b.x], base + 5u);
    atomicMax(&g_winner[b.y], base + 6u);
    atomicMax(&g_winner[b.z], base + 7u);
    atomicMax(&g_winner[b.w], base + 8u);
}

// count8 = N_OUT/8 threads, each produces 8 outputs.
__global__ void compact_kernel(float* __restrict__ out,
                               const float* __restrict__ x,
                               int count8) {
    int t = blockIdx.x * blockDim.x + threadIdx.x;
    if (t >= count8) return;

    const uint4* __restrict__ sp = reinterpret_cast<const uint4*>(g_winner);
    float4* __restrict__ op = reinterpret_cast<float4*>(out);

    // Scratch is dead after this read: stream it (evict-first).
    uint4 w0 = __ldcs(&sp[2 * t + 0]);
    uint4 w1 = __ldcs(&sp[2 * t + 1]);

    float4 o0, o1;
    o0.x = w0.x ? __ldg(&x[w0.x - 1u]) : 0.0f;
    o0.y = w0.y ? __ldg(&x[w0.y - 1u]) : 0.0f;
    o0.z = w0.z ? __ldg(&x[w0.z - 1u]) : 0.0f;
    o0.w = w0.w ? __ldg(&x[w0.w - 1u]) : 0.0f;
    o1.x = w1.x ? __ldg(&x[w1.x - 1u]) : 0.0f;
    o1.y = w1.y ? __ldg(&x[w1.y - 1u]) : 0.0f;
    o1.z = w1.z ? __ldg(&x[w1.z - 1u]) : 0.0f;
    o1.w = w1.w ? __ldg(&x[w1.w - 1u]) : 0.0f;

    // out is write-once: streaming store, don't evict x/scratch.
    __stcs(&op[2 * t + 0], o0);
    __stcs(&op[2 * t + 1], o1);
}

extern "C" void kernel_launch(void* const* d_in, const int* in_sizes, int n_in,
                              void* d_out, int out_size) {
    const float* x = reinterpret_cast<const float*>(d_in[0]);
    const int* pos = reinterpret_cast<const int*>(d_in[1]);
    float* out     = reinterpret_cast<float*>(d_out);

    int n = in_sizes[0];             // 6,422,528 (divisible by 8)
    int n8 = n / 8;
    int count16 = out_size / 16;     // 1,605,632
    int count8  = out_size / 8;      // 3,211,264

    const int T = 256;

    // Z: zero the winner scratch (heats it in L2 right before the atomics).
    zero_scratch_kernel<<<(count16 + T - 1) / T, T>>>(count16);

    // S: deterministic last-index-wins via 32-bit atomicMax, 8/thread.
    scatter_kernel<<<(n8 + T - 1) / T, T>>>(
        reinterpret_cast<const int4*>(pos), n8);

    // C: gather winners' values, zero-fill empties, stream out.
    compact_kernel<<<(count8 + T - 1) / T, T>>>(out, x, count8);
}